// round 7
// baseline (speedup 1.0000x reference)
#include <cuda_runtime.h>
#include <cuda_fp16.h>
#include <cstdint>

// ---------------------------------------------------------------------------
// QuantizedEmbedding (VQ-VAE codebook + EMA update), GB300 sm_103a
// Round 6: int8 IMMA (m16n8k32) argmin GEMM @ 2x fp16 rate,
//          per-(thread,row) top-3 -> global top-4 -> exact fp32 rescore.
// ---------------------------------------------------------------------------

#define KC   8192
#define DD   256
#define NP   32768
#define GMA  0.99f
#define OMG  0.01f
#define EPSV 1e-5f

#define OFF_ZQ     0LL
#define OFF_COMMIT 8388608LL
#define OFF_IDX    8388609LL
#define OFF_EW     8421377LL
#define OFF_MT     10518529LL
#define OFF_NT     12615681LL

// ---- device scratch ----
__device__ __align__(256) int8_t g_Aq[(size_t)NP * DD];   // 8.4 MB int8 points
__device__ __align__(256) int8_t g_Bq[(size_t)KC * DD];   // 2.1 MB int8 codes
__device__ float g_zscale[NP];
__device__ float g_wscale[KC];
__device__ float g_wsq[KC];
__device__ int4  g_cand[NP];
__device__ float g_nt[KC];
__device__ float g_st[KC * DD];
__device__ float g_commit;
__device__ float g_nsum;
__device__ float g_NtNew[KC];

// ===========================================================================
// helpers
// ===========================================================================
__device__ __forceinline__ uint32_t smem_u32(const void* p) {
    uint32_t a;
    asm("{ .reg .u64 t; cvta.to.shared.u64 t, %1; cvt.u32.u64 %0, t; }"
        : "=r"(a) : "l"(p));
    return a;
}
__device__ __forceinline__ void cp16(uint32_t dst, const void* src) {
    asm volatile("cp.async.cg.shared.global [%0], [%1], 16;"
                 :: "r"(dst), "l"(src) : "memory");
}
__device__ __forceinline__ void cp_commit() {
    asm volatile("cp.async.commit_group;" ::: "memory");
}
__device__ __forceinline__ void cp_wait2() {
    asm volatile("cp.async.wait_group 2;" ::: "memory");
}
__device__ __forceinline__ void ldsm4(uint32_t* r, uint32_t addr) {
    asm volatile("ldmatrix.sync.aligned.m8n8.x4.shared.b16 {%0,%1,%2,%3}, [%4];"
                 : "=r"(r[0]), "=r"(r[1]), "=r"(r[2]), "=r"(r[3]) : "r"(addr));
}
// int8 x int8 -> s32 accumulate, k=32
__device__ __forceinline__ void imma16832(int* c, const uint32_t* a,
                                          uint32_t b0, uint32_t b1) {
    asm volatile(
        "mma.sync.aligned.m16n8k32.row.col.s32.s8.s8.s32 "
        "{%0,%1,%2,%3}, {%4,%5,%6,%7}, {%8,%9}, {%0,%1,%2,%3};"
        : "+r"(c[0]), "+r"(c[1]), "+r"(c[2]), "+r"(c[3])
        : "r"(a[0]), "r"(a[1]), "r"(a[2]), "r"(a[3]), "r"(b0), "r"(b1));
}
__device__ __forceinline__ unsigned fmono(float f) {
    unsigned u = __float_as_uint(f);
    return (u & 0x80000000u) ? ~u : (u | 0x80000000u);
}
__device__ __forceinline__ void ins4(unsigned long long* a, unsigned long long v) {
    if (v < a[3]) {
        if (v < a[2]) {
            a[3] = a[2];
            if (v < a[1]) {
                a[2] = a[1];
                if (v < a[0]) { a[1] = a[0]; a[0] = v; } else a[1] = v;
            } else a[2] = v;
        } else a[3] = v;
    }
}

// ===========================================================================
// small kernels
// ===========================================================================
__global__ void zero_kernel() {
    long long i = (long long)blockIdx.x * blockDim.x + threadIdx.x;
    long long stride = (long long)gridDim.x * blockDim.x;
    for (long long j = i; j < (long long)KC * DD; j += stride) g_st[j] = 0.0f;
    for (long long j = i; j < KC; j += stride) g_nt[j] = 0.0f;
    if (i == 0) { g_commit = 0.0f; g_nsum = 0.0f; }
}

// per-row int8 quantization; warp per row (8 rows / 256-thread block)
template <bool WITH_WSQ>
__device__ __forceinline__ void quant_row(const float* __restrict__ src,
                                          int8_t* __restrict__ dst,
                                          float* __restrict__ scale_out,
                                          float* __restrict__ wsq_out,
                                          int row, int lane) {
    const float* rp = src + (size_t)row * DD + lane * 8;
    float4 v0 = *reinterpret_cast<const float4*>(rp);
    float4 v1 = *reinterpret_cast<const float4*>(rp + 4);
    float f[8] = {v0.x, v0.y, v0.z, v0.w, v1.x, v1.y, v1.z, v1.w};
    float amax = 0.0f, ssq = 0.0f;
    #pragma unroll
    for (int i = 0; i < 8; i++) {
        amax = fmaxf(amax, fabsf(f[i]));
        if (WITH_WSQ) ssq += f[i] * f[i];
    }
    #pragma unroll
    for (int o = 16; o; o >>= 1) {
        amax = fmaxf(amax, __shfl_xor_sync(0xFFFFFFFFu, amax, o));
        if (WITH_WSQ) ssq += __shfl_xor_sync(0xFFFFFFFFu, ssq, o);
    }
    const float inv = (amax > 0.0f) ? (127.0f / amax) : 0.0f;
    uint32_t pk[2] = {0u, 0u};
    #pragma unroll
    for (int i = 0; i < 8; i++) {
        int q = __float2int_rn(f[i] * inv);
        pk[i >> 2] |= ((uint32_t)(q & 0xFF)) << ((i & 3) * 8);
    }
    *reinterpret_cast<uint2*>(dst + (size_t)row * DD + lane * 8) =
        make_uint2(pk[0], pk[1]);
    if (lane == 0) {
        scale_out[row] = amax * (1.0f / 127.0f);
        if (WITH_WSQ) wsq_out[row] = ssq;
    }
}

__global__ void conv_ze_kernel(const float* __restrict__ ze) {
    int row = blockIdx.x * 8 + (threadIdx.x >> 5);
    quant_row<false>(ze, g_Aq, g_zscale, nullptr, row, threadIdx.x & 31);
}
__global__ void conv_w_kernel(const float* __restrict__ W) {
    int row = blockIdx.x * 8 + (threadIdx.x >> 5);
    quant_row<true>(W, g_Bq, g_wscale, g_wsq, row, threadIdx.x & 31);
}

// ===========================================================================
// IMMA argmin GEMM.
//   CTA: 128 points x 8192 codes. A resident (2 k128-chunks, 32 KB).
//   B streamed: 64 N-tiles of 128 codes x 2 k128-chunks, 4-buffer cp.async
//   ring (16 KB each). 8 warps = 2(M) x 4(N); warp tile 64x32; m16n8k32 s8.
//   Epilogue: score = wsq - 2*sz*sw*idot; per-(thread,row) top-3;
//   hierarchical merge -> global top-4 per point -> exact fp32 rescore.
// ===========================================================================
#define GTOT   128              // 64 n-tiles * 2 k-chunks
#define SM_A_BYTES 32768
#define SM_B_BYTES 65536        // 4 x 16 KB
#define SMEM_BYTES (SM_A_BYTES + SM_B_BYTES)

__device__ __forceinline__ void load_B_chunk(uint32_t dstBase, int nt, int kc,
                                             int tid) {
    const int8_t* src0 = g_Bq + (size_t)nt * 128 * DD + kc * 128;
    #pragma unroll
    for (int i = 0; i < 4; i++) {
        int v = tid + 256 * i;          // 0..1023
        int row = v >> 3, c = v & 7;    // row: code in tile, c: 16B chunk
        const void* src = src0 + (size_t)row * DD + c * 16;
        uint32_t dst = dstBase + row * 128 + (((c ^ (row & 7))) << 4);
        cp16(dst, src);
    }
}

__global__ void __launch_bounds__(256, 1) argmin_gemm_kernel() {
    extern __shared__ char smem[];
    const uint32_t sb = smem_u32(smem);
    const uint32_t Ab = sb;
    const uint32_t Bb = sb + SM_A_BYTES;

    const int tid  = threadIdx.x;
    const int lane = tid & 31;
    const int wid  = tid >> 5;
    const int R0   = (wid >> 2) * 64;     // warp M offset (0/64)
    const int C0   = (wid & 3) * 32;      // warp N offset within tile
    const int n0   = blockIdx.x * 128;

    // ---- prologue: A (resident, 2 chunks) + B chunks g=0,1 ----
    #pragma unroll
    for (int i = 0; i < 8; i++) {
        int v = tid + 256 * i;            // 0..2047
        int row = v >> 4, gc = v & 15;    // 16 x 16B per 256B row
        int kc = gc >> 3, c = gc & 7;
        const void* src = g_Aq + (size_t)(n0 + row) * DD + gc * 16;
        uint32_t dst = Ab + kc * 16384 + row * 128 + (((c ^ (row & 7))) << 4);
        cp16(dst, src);
    }
    load_B_chunk(Bb + 0 * 16384, 0, 0, tid);
    cp_commit();
    load_B_chunk(Bb + 1 * 16384, 0, 1, tid);
    cp_commit();

    // per-lane ldmatrix row components
    const int rl = (lane & 7) | (((lane >> 3) & 1) << 3);  // 0..15
    const int kh = (lane >> 4) & 1;                        // 16B half select

    // per-thread row scales (M rows this thread's C fragment touches)
    float szr[8];
    #pragma unroll
    for (int t = 0; t < 4; t++)
        #pragma unroll
        for (int h = 0; h < 2; h++)
            szr[t * 2 + h] = g_zscale[n0 + R0 + t * 16 + (lane >> 2) + h * 8];

    int acc[4][4][4];
    #pragma unroll
    for (int t = 0; t < 4; t++)
        #pragma unroll
        for (int j = 0; j < 4; j++)
            #pragma unroll
            for (int e = 0; e < 4; e++) acc[t][j][e] = 0;

    const float FINF = __int_as_float(0x7f800000);
    float s1[8], s2[8], s3[8]; int i1[8], i2[8], i3[8];
    #pragma unroll
    for (int r = 0; r < 8; r++) {
        s1[r] = FINF; s2[r] = FINF; s3[r] = FINF;
        i1[r] = 0; i2[r] = 0; i3[r] = 0;
    }

    for (int g = 0; g < GTOT; ++g) {
        const int kc = g & 1, nt = g >> 1;
        if (g + 2 < GTOT)
            load_B_chunk(Bb + ((g + 2) & 3) * 16384, (g + 2) >> 1, (g + 2) & 1, tid);
        cp_commit();
        cp_wait2();
        __syncthreads();

        const uint32_t Bbuf = Bb + (g & 3) * 16384;
        const uint32_t Achk = Ab + kc * 16384;

        #pragma unroll
        for (int s = 0; s < 4; s++) {           // 4 x k32 per 128B chunk
            const int c16 = s * 2 + kh;
            uint32_t a[4][4];
            #pragma unroll
            for (int t = 0; t < 4; t++) {
                int row = R0 + t * 16 + rl;
                uint32_t addr = Achk + row * 128 + (((c16 ^ (row & 7))) << 4);
                ldsm4(a[t], addr);
            }
            uint32_t bf[4][2];
            #pragma unroll
            for (int p = 0; p < 2; p++) {
                int row = C0 + p * 16 + rl;
                uint32_t addr = Bbuf + row * 128 + (((c16 ^ (row & 7))) << 4);
                uint32_t r4[4];
                ldsm4(r4, addr);
                bf[2 * p][0] = r4[0]; bf[2 * p][1] = r4[2];
                bf[2 * p + 1][0] = r4[1]; bf[2 * p + 1][1] = r4[3];
            }
            #pragma unroll
            for (int t = 0; t < 4; t++)
                #pragma unroll
                for (int j = 0; j < 4; j++)
                    imma16832(acc[t][j], a[t], bf[j][0], bf[j][1]);
        }

        if (kc == 1) {
            // fold tile nt into running top-3 per (thread,row); reset acc
            const int cb0 = nt * 128 + C0 + (lane & 3) * 2;
            #pragma unroll
            for (int j = 0; j < 4; j++) {
                const int col = cb0 + j * 8;
                const float2 wq = *reinterpret_cast<const float2*>(&g_wsq[col]);
                const float2 ws = *reinterpret_cast<const float2*>(&g_wscale[col]);
                #pragma unroll
                for (int t = 0; t < 4; t++) {
                    #pragma unroll
                    for (int e = 0; e < 4; e++) {
                        const int lr = t * 2 + (e >> 1);
                        const float fd = (float)acc[t][j][e];
                        const float swv = (e & 1) ? ws.y : ws.x;
                        const float wqv = (e & 1) ? wq.y : wq.x;
                        const float sc = fmaf(-2.0f * szr[lr] * swv, fd, wqv);
                        const int cc = col + (e & 1);
                        if (sc < s1[lr]) {
                            s3[lr] = s2[lr]; i3[lr] = i2[lr];
                            s2[lr] = s1[lr]; i2[lr] = i1[lr];
                            s1[lr] = sc;     i1[lr] = cc;
                        } else if (sc < s2[lr]) {
                            s3[lr] = s2[lr]; i3[lr] = i2[lr];
                            s2[lr] = sc;     i2[lr] = cc;
                        } else if (sc < s3[lr]) {
                            s3[lr] = sc;     i3[lr] = cc;
                        }
                        acc[t][j][e] = 0;
                    }
                }
            }
        }
    }

    // ---- final reduction: quad merge -> smem -> per-row top-4 ----
    unsigned long long* red = reinterpret_cast<unsigned long long*>(smem + SM_A_BYTES);
    const int ni = wid & 3;
    __syncthreads();   // everyone past last compute before aliasing B as red

    #pragma unroll
    for (int r = 0; r < 8; r++) {
        const int t = r >> 1, h = r & 1;
        const int row = R0 + t * 16 + (lane >> 2) + h * 8;
        unsigned long long arr[4];
        arr[0] = ((unsigned long long)fmono(s1[r]) << 32) | (unsigned)i1[r];
        arr[1] = ((unsigned long long)fmono(s2[r]) << 32) | (unsigned)i2[r];
        arr[2] = ((unsigned long long)fmono(s3[r]) << 32) | (unsigned)i3[r];
        arr[3] = ~0ull;
        #pragma unroll
        for (int off = 1; off <= 2; off <<= 1) {
            unsigned long long o0 = __shfl_xor_sync(0xFFFFFFFFu, arr[0], off);
            unsigned long long o1 = __shfl_xor_sync(0xFFFFFFFFu, arr[1], off);
            unsigned long long o2 = __shfl_xor_sync(0xFFFFFFFFu, arr[2], off);
            unsigned long long o3 = __shfl_xor_sync(0xFFFFFFFFu, arr[3], off);
            ins4(arr, o0); ins4(arr, o1); ins4(arr, o2); ins4(arr, o3);
        }
        if ((lane & 3) == 0) {
            #pragma unroll
            for (int k = 0; k < 4; k++) red[(row * 4 + ni) * 4 + k] = arr[k];
        }
    }
    __syncthreads();

    if (tid < 128) {
        unsigned long long a[4] = {~0ull, ~0ull, ~0ull, ~0ull};
        #pragma unroll
        for (int w = 0; w < 4; w++)
            #pragma unroll
            for (int k = 0; k < 4; k++) ins4(a, red[(tid * 4 + w) * 4 + k]);
        g_cand[n0 + tid] = make_int4((int)(a[0] & 0xFFFFFFFFu),
                                     (int)(a[1] & 0xFFFFFFFFu),
                                     (int)(a[2] & 0xFFFFFFFFu),
                                     (int)(a[3] & 0xFFFFFFFFu));
    }
}

// ===========================================================================
// Exact fp32 rescore of top-4 + gather zq + EMA scatter + commit partials
// ===========================================================================
__global__ void rescore_gather_kernel(const float* __restrict__ ze,
                                      const float* __restrict__ W,
                                      float* __restrict__ out) {
    const int n = blockIdx.x;
    const int d = threadIdx.x;
    const int4 c = g_cand[n];
    const float z = ze[(size_t)n * DD + d];
    float w[4], p[4];
    w[0] = W[(size_t)c.x * DD + d];
    w[1] = W[(size_t)c.y * DD + d];
    w[2] = W[(size_t)c.z * DD + d];
    w[3] = W[(size_t)c.w * DD + d];
    #pragma unroll
    for (int j = 0; j < 4; j++) p[j] = z * w[j];
    #pragma unroll
    for (int o = 16; o; o >>= 1)
        #pragma unroll
        for (int j = 0; j < 4; j++)
            p[j] += __shfl_down_sync(0xFFFFFFFFu, p[j], o);
    __shared__ float rp[8][4];
    __shared__ int spick;
    const int lw = d >> 5, ln = d & 31;
    if (ln == 0) {
        #pragma unroll
        for (int j = 0; j < 4; j++) rp[lw][j] = p[j];
    }
    __syncthreads();
    if (d == 0) {
        int ci[4] = {c.x, c.y, c.z, c.w};
        float bs = __int_as_float(0x7f800000);   // +inf
        int bi = 0x7FFFFFFF, bj = 0;
        #pragma unroll
        for (int j = 0; j < 4; j++) {
            float dot = 0.0f;
            #pragma unroll
            for (int i = 0; i < 8; i++) dot += rp[i][j];
            float s = fmaf(-2.0f, dot, g_wsq[ci[j]]);
            if (s < bs || (s == bs && ci[j] < bi)) { bs = s; bi = ci[j]; bj = j; }
        }
        spick = bj;
    }
    __syncthreads();
    const int pick = spick;
    const int cb = (pick == 0) ? c.x : (pick == 1) ? c.y : (pick == 2) ? c.z : c.w;
    const float wv = (pick == 0) ? w[0] : (pick == 1) ? w[1]
                   : (pick == 2) ? w[2] : w[3];
    out[OFF_ZQ + (size_t)n * DD + d] = wv;
    const float diff = wv - z;
    float sq = diff * diff;
    atomicAdd(&g_st[(size_t)cb * DD + d], z);
    #pragma unroll
    for (int o = 16; o; o >>= 1) sq += __shfl_down_sync(0xFFFFFFFFu, sq, o);
    __shared__ float red[8];
    if (ln == 0) red[lw] = sq;
    __syncthreads();
    if (lw == 0) {
        float v = (ln < 8) ? red[ln] : 0.0f;
        #pragma unroll
        for (int o = 4; o; o >>= 1) v += __shfl_down_sync(0xFFFFFFFFu, v, o);
        if (ln == 0) atomicAdd(&g_commit, v);
    }
    if (d == 0) {
        atomicAdd(&g_nt[cb], 1.0f);
        out[OFF_IDX + n] = (float)cb;
    }
}

// ===========================================================================
// Nt / final
// ===========================================================================
__global__ void nt_kernel(const float* __restrict__ Nt, float* __restrict__ out) {
    int k = blockIdx.x * 256 + threadIdx.x;
    float v = GMA * Nt[k] + OMG * g_nt[k];
    g_NtNew[k] = v;
    out[OFF_NT + k] = v;
    float s = v;
    #pragma unroll
    for (int o = 16; o; o >>= 1) s += __shfl_down_sync(0xFFFFFFFFu, s, o);
    __shared__ float red[8];
    int wid = threadIdx.x >> 5, lane = threadIdx.x & 31;
    if (lane == 0) red[wid] = s;
    __syncthreads();
    if (wid == 0) {
        float v2 = (lane < 8) ? red[lane] : 0.0f;
        #pragma unroll
        for (int o = 4; o; o >>= 1) v2 += __shfl_down_sync(0xFFFFFFFFu, v2, o);
        if (lane == 0) atomicAdd(&g_nsum, v2);
    }
}

__global__ void final_kernel(const float* __restrict__ mt, float* __restrict__ out) {
    long long i = (long long)blockIdx.x * 256 + threadIdx.x;
    int k = (int)(i >> 8);
    float mtn = GMA * mt[i] + OMG * g_st[i];
    out[OFF_MT + i] = mtn;
    float n = g_nsum;
    float Nn = (g_NtNew[k] + EPSV) * n / (n + (float)KC * EPSV);
    out[OFF_EW + i] = mtn / Nn;
    if (i == 0) out[OFF_COMMIT] = g_commit / (float)((long long)NP * DD);
}

// ===========================================================================
extern "C" void kernel_launch(void* const* d_in, const int* in_sizes, int n_in,
                              void* d_out, int out_size) {
    const float* ze = (const float*)d_in[0];
    const float* W  = (const float*)d_in[1];
    const float* mt = (const float*)d_in[2];
    const float* Nt = (const float*)d_in[3];
    float* out = (float*)d_out;
    (void)in_sizes; (void)n_in; (void)out_size;

    cudaFuncSetAttribute(argmin_gemm_kernel,
                         cudaFuncAttributeMaxDynamicSharedMemorySize, SMEM_BYTES);

    zero_kernel<<<2048, 256>>>();
    conv_ze_kernel<<<NP / 8, 256>>>(ze);
    conv_w_kernel<<<KC / 8, 256>>>(W);
    argmin_gemm_kernel<<<NP / 128, 256, SMEM_BYTES>>>();
    rescore_gather_kernel<<<NP, 256>>>(ze, W, out);
    nt_kernel<<<KC / 256, 256>>>(Nt, out);
    final_kernel<<<(KC * DD) / 256, 256>>>(mt, out);
}